// round 9
// baseline (speedup 1.0000x reference)
#include <cuda_runtime.h>
#include <cuda_fp16.h>
#include <stdint.h>
#include <math.h>

#define B_DIM 2
#define S_DIM 2048
#define M_DIM 1024
#define NHEAD 16
#define HDIM 64
#define FFN_H 2048
#define TOK (B_DIM * S_DIM)          // 4096
#define QKV_N (3 * M_DIM)            // 3072
#define NEGV -1e9f

// ------------------------- scratch (static device) -------------------------
__device__ float g_Wqkv[M_DIM * QKV_N];        // packed [K=1024, N=3072]
__device__ float g_bqkv[QKV_N];
__device__ float g_qkv[TOK * QKV_N];
__device__ float g_ctx[TOK * M_DIM];
__device__ float g_attnproj[TOK * M_DIM];
__device__ float g_y[TOK * M_DIM];
__device__ float g_ffh[TOK * FFN_H];
__device__ float g_ffo[TOK * M_DIM];

// ------------------------- helpers ------------------------------------
__device__ __forceinline__ float tf32r(float x) {
    unsigned r; asm("cvt.rna.tf32.f32 %0, %1;" : "=r"(r) : "f"(x));
    return __uint_as_float(r);
}
// tf32 m16n8k8 (attention)
__device__ __forceinline__ void mma8(float* c, const unsigned* a, const unsigned* b) {
    asm volatile(
        "mma.sync.aligned.m16n8k8.row.col.f32.tf32.tf32.f32 "
        "{%0,%1,%2,%3},{%4,%5,%6,%7},{%8,%9},{%0,%1,%2,%3};"
        : "+f"(c[0]), "+f"(c[1]), "+f"(c[2]), "+f"(c[3])
        : "r"(a[0]), "r"(a[1]), "r"(a[2]), "r"(a[3]), "r"(b[0]), "r"(b[1]));
}
// fp16 m16n8k16, fp32 accumulate (GEMMs)
__device__ __forceinline__ void mma16(float* c, const unsigned* a, const unsigned* b) {
    asm volatile(
        "mma.sync.aligned.m16n8k16.row.col.f32.f16.f16.f32 "
        "{%0,%1,%2,%3},{%4,%5,%6,%7},{%8,%9},{%0,%1,%2,%3};"
        : "+f"(c[0]), "+f"(c[1]), "+f"(c[2]), "+f"(c[3])
        : "r"(a[0]), "r"(a[1]), "r"(a[2]), "r"(a[3]), "r"(b[0]), "r"(b[1]));
}
__device__ __forceinline__ unsigned f2h2(float lo, float hi) {
    __half2 h = __floats2half2_rn(lo, hi);
    return *(unsigned*)&h;
}

// ------------------------- weight repack -----------------------------------
__global__ void pack_qkv_kernel(const float* __restrict__ Wq,
                                const float* __restrict__ Wk,
                                const float* __restrict__ Wv,
                                const float* __restrict__ bq,
                                const float* __restrict__ bk,
                                const float* __restrict__ bv) {
    int idx = blockIdx.x * blockDim.x + threadIdx.x;
    if (idx < M_DIM * QKV_N) {
        int n = idx % QKV_N;
        int k = idx / QKV_N;
        int which = n / M_DIM;
        int hd = n % M_DIM;
        int h = hd / HDIM, d = hd % HDIM;
        const float* W = (which == 0) ? Wq : (which == 1) ? Wk : Wv;
        g_Wqkv[idx] = W[((size_t)h * M_DIM + k) * HDIM + d];
    }
    if (idx < QKV_N) {
        int which = idx / M_DIM;
        int hd = idx % M_DIM;
        const float* bb = (which == 0) ? bq : (which == 1) ? bk : bv;
        g_bqkv[idx] = bb[hd];
    }
}

// ------------------------- fp16 tensor-core GEMM ---------------------------
// C[M,N] = A[M,K]@B[K,N] + bias (fp32 accum), optional ReLU.
// Tile 128x128, K-step 16, 256 thr = 8 warps (2x4), warp tile 64x32.
// SMEM (32-bit words holding half2 k-pairs):
//   As[2][128][12]  (k-pairs along row; row pad 12 words, conflict-free)
//   Bs[2][8][136]   (k-pair-major: word = (B[2r][n], B[2r+1][n]); pad 136)
template <bool RELU>
__global__ __launch_bounds__(256, 2)
void gemm_tc(const float* __restrict__ A, const float* __restrict__ Bm,
             const float* __restrict__ bias, float* __restrict__ C,
             int M, int N, int K) {
    extern __shared__ unsigned smw[];
    unsigned* As = smw;                // 2 * 1536
    unsigned* Bs = smw + 2 * 1536;     // 2 * 1088

    const int tid = threadIdx.x, lane = tid & 31, w = tid >> 5;
    const int wm = w >> 2, wn = w & 3;
    const int g = lane >> 2, tg = lane & 3;
    const int row0 = blockIdx.y * 128, col0 = blockIdx.x * 128;

    const int ar = tid >> 2, ac = (tid & 3) * 4;     // A rows ar, ar+64; k offs ac..ac+3
    const int bc = (tid & 31) * 4;                   // B: warp w -> k rows 2w,2w+1

    float4 stA[2], stB[2];
    float acc[4][4][4];
#pragma unroll
    for (int i = 0; i < 4; i++)
#pragma unroll
        for (int j = 0; j < 4; j++)
#pragma unroll
            for (int q = 0; q < 4; q++) acc[i][j][q] = 0.f;

    const int nk = K >> 4;

    auto stage_store = [&](int s) {
        // A: rows ar, ar+64; 4 consecutive k -> 2 half2 words
#pragma unroll
        for (int i = 0; i < 2; i++) {
            float4 v = stA[i];
            unsigned* ad = &As[s * 1536 + (ar + i * 64) * 12 + (ac >> 1)];
            ad[0] = f2h2(v.x, v.y);
            ad[1] = f2h2(v.z, v.w);
        }
        // B: pair k rows (2w, 2w+1) per n -> 4 words, one 16B store
        unsigned* bd = &Bs[s * 1088 + w * 136 + bc];
        uint4 pk;
        pk.x = f2h2(stB[0].x, stB[1].x);
        pk.y = f2h2(stB[0].y, stB[1].y);
        pk.z = f2h2(stB[0].z, stB[1].z);
        pk.w = f2h2(stB[0].w, stB[1].w);
        *(uint4*)bd = pk;
    };

    // prologue: load + store stage 0
    {
        const float* Ap = A + (size_t)(row0 + ar) * K + ac;
        stA[0] = *(const float4*)Ap;
        stA[1] = *(const float4*)(Ap + (size_t)64 * K);
        const float* Bp = Bm + (size_t)(2 * w) * N + col0 + bc;
        stB[0] = *(const float4*)Bp;
        stB[1] = *(const float4*)(Bp + N);
        stage_store(0);
    }
    __syncthreads();

    for (int kt = 0; kt < nk; kt++) {
        const int cur = kt & 1;
        if (kt + 1 < nk) {
            const int k0 = (kt + 1) << 4;
            const float* Ap = A + (size_t)(row0 + ar) * K + k0 + ac;
            stA[0] = *(const float4*)Ap;
            stA[1] = *(const float4*)(Ap + (size_t)64 * K);
            const float* Bp = Bm + (size_t)(k0 + 2 * w) * N + col0 + bc;
            stB[0] = *(const float4*)Bp;
            stB[1] = *(const float4*)(Bp + N);
        }

        const unsigned* as = As + cur * 1536;
        const unsigned* bs = Bs + cur * 1088;
        unsigned af[4][4];
#pragma unroll
        for (int mi = 0; mi < 4; mi++) {
            const unsigned* ap = as + (wm * 64 + mi * 16) * 12;
            af[mi][0] = ap[g * 12 + tg];
            af[mi][1] = ap[(g + 8) * 12 + tg];
            af[mi][2] = ap[g * 12 + tg + 4];
            af[mi][3] = ap[(g + 8) * 12 + tg + 4];
        }
#pragma unroll
        for (int ni = 0; ni < 4; ni++) {
            unsigned bf[2];
            const int ncol = wn * 32 + ni * 8 + g;
            bf[0] = bs[tg * 136 + ncol];
            bf[1] = bs[(tg + 4) * 136 + ncol];
#pragma unroll
            for (int mi = 0; mi < 4; mi++) mma16(acc[mi][ni], af[mi], bf);
        }

        if (kt + 1 < nk) stage_store((kt + 1) & 1);
        __syncthreads();
    }

    // epilogue
#pragma unroll
    for (int mi = 0; mi < 4; mi++) {
        const int r = row0 + wm * 64 + mi * 16 + g;
#pragma unroll
        for (int ni = 0; ni < 4; ni++) {
            const int c = col0 + wn * 32 + ni * 8 + 2 * tg;
            const float b0 = bias[c], b1 = bias[c + 1];
            float v0 = acc[mi][ni][0] + b0, v1 = acc[mi][ni][1] + b1;
            float v2 = acc[mi][ni][2] + b0, v3 = acc[mi][ni][3] + b1;
            if (RELU) {
                v0 = fmaxf(v0, 0.f); v1 = fmaxf(v1, 0.f);
                v2 = fmaxf(v2, 0.f); v3 = fmaxf(v3, 0.f);
            }
            *(float2*)&C[(size_t)r * N + c] = make_float2(v0, v1);
            *(float2*)&C[(size_t)(r + 8) * N + c] = make_float2(v2, v3);
        }
    }
}

// ------------------------- tf32 flash attention ----------------------------
// grid (S/128, B*H), 256 thr = 8 warps; warp = 16 queries; key tile 64.
__global__ __launch_bounds__(256, 2)
void attn_tc(const float* __restrict__ qkv, const int* __restrict__ mask,
             float* __restrict__ ctx) {
    extern __shared__ float sm[];
    float* Ks  = sm;                       // [64][68]
    float* Vs  = sm + 64 * 68;             // [64][68]
    float* Pw0 = sm + 2 * 64 * 68;         // [8][16][68]
    float* Ms  = Pw0 + 8 * 16 * 68;        // [64]

    const int tid = threadIdx.x, lane = tid & 31, w = tid >> 5;
    const int g = lane >> 2, tg = lane & 3;
    const int bh = blockIdx.y, b = bh >> 4, h = bh & 15;
    const int qw = blockIdx.x * 128 + w * 16;
    float* Pw = Pw0 + w * 16 * 68;

    unsigned qf[8][4];
    {
        const float* qb = qkv + (size_t)(b * S_DIM + qw) * QKV_N + h * HDIM;
#pragma unroll
        for (int fk = 0; fk < 8; fk++) {
            qf[fk][0] = __float_as_uint(tf32r(qb[(size_t)g * QKV_N + fk * 8 + tg] * 0.125f));
            qf[fk][1] = __float_as_uint(tf32r(qb[(size_t)(g + 8) * QKV_N + fk * 8 + tg] * 0.125f));
            qf[fk][2] = __float_as_uint(tf32r(qb[(size_t)g * QKV_N + fk * 8 + tg + 4] * 0.125f));
            qf[fk][3] = __float_as_uint(tf32r(qb[(size_t)(g + 8) * QKV_N + fk * 8 + tg + 4] * 0.125f));
        }
    }

    float of[8][4];
#pragma unroll
    for (int i = 0; i < 8; i++) { of[i][0] = of[i][1] = of[i][2] = of[i][3] = 0.f; }
    float m0 = -INFINITY, m1 = -INFINITY, l0 = 0.f, l1 = 0.f;

    const int kr = tid >> 4, kc = (tid & 15) * 4;

    for (int kt = 0; kt < S_DIM; kt += 64) {
        __syncthreads();
#pragma unroll
        for (int i = 0; i < 4; i++) {
            const int r = kr + i * 16;
            const float* kb = qkv + (size_t)(b * S_DIM + kt + r) * QKV_N + M_DIM + h * HDIM + kc;
            float4 kv = *(const float4*)kb;
            float4 vv = *(const float4*)(kb + M_DIM);
            float* kd = &Ks[r * 68 + kc];
            kd[0] = tf32r(kv.x); kd[1] = tf32r(kv.y);
            kd[2] = tf32r(kv.z); kd[3] = tf32r(kv.w);
            float* vd = &Vs[r * 68 + kc];
            vd[0] = tf32r(vv.x); vd[1] = tf32r(vv.y);
            vd[2] = tf32r(vv.z); vd[3] = tf32r(vv.w);
        }
        if (tid < 64) Ms[tid] = mask[b * S_DIM + kt + tid] ? 0.f : NEGV;
        __syncthreads();

        float s[8][4];
#pragma unroll
        for (int fn = 0; fn < 8; fn++) { s[fn][0] = s[fn][1] = s[fn][2] = s[fn][3] = 0.f; }
#pragma unroll
        for (int fk = 0; fk < 8; fk++) {
#pragma unroll
            for (int fn = 0; fn < 8; fn++) {
                unsigned bf[2];
                bf[0] = __float_as_uint(Ks[(fn * 8 + g) * 68 + fk * 8 + tg]);
                bf[1] = __float_as_uint(Ks[(fn * 8 + g) * 68 + fk * 8 + tg + 4]);
                mma8(s[fn], qf[fk], bf);
            }
        }

        float mx0 = -INFINITY, mx1 = -INFINITY;
#pragma unroll
        for (int fn = 0; fn < 8; fn++) {
            const float mk0 = Ms[fn * 8 + 2 * tg], mk1 = Ms[fn * 8 + 2 * tg + 1];
            s[fn][0] += mk0; s[fn][1] += mk1;
            s[fn][2] += mk0; s[fn][3] += mk1;
            mx0 = fmaxf(mx0, fmaxf(s[fn][0], s[fn][1]));
            mx1 = fmaxf(mx1, fmaxf(s[fn][2], s[fn][3]));
        }
        mx0 = fmaxf(mx0, __shfl_xor_sync(0xffffffffu, mx0, 1));
        mx0 = fmaxf(mx0, __shfl_xor_sync(0xffffffffu, mx0, 2));
        mx1 = fmaxf(mx1, __shfl_xor_sync(0xffffffffu, mx1, 1));
        mx1 = fmaxf(mx1, __shfl_xor_sync(0xffffffffu, mx1, 2));
        const float nm0 = fmaxf(m0, mx0), nm1 = fmaxf(m1, mx1);
        const float a0 = __expf(m0 - nm0), a1 = __expf(m1 - nm1);
        m0 = nm0; m1 = nm1;
        l0 *= a0; l1 *= a1;
#pragma unroll
        for (int fn = 0; fn < 8; fn++) {
            of[fn][0] *= a0; of[fn][1] *= a0;
            of[fn][2] *= a1; of[fn][3] *= a1;
            float p0 = tf32r(__expf(s[fn][0] - m0));
            float p1 = tf32r(__expf(s[fn][1] - m0));
            float p2 = tf32r(__expf(s[fn][2] - m1));
            float p3 = tf32r(__expf(s[fn][3] - m1));
            l0 += p0 + p1; l1 += p2 + p3;
            *(float2*)&Pw[g * 68 + fn * 8 + 2 * tg] = make_float2(p0, p1);
            *(float2*)&Pw[(g + 8) * 68 + fn * 8 + 2 * tg] = make_float2(p2, p3);
        }
        __syncwarp();

#pragma unroll
        for (int fk = 0; fk < 8; fk++) {
            unsigned af[4];
            af[0] = __float_as_uint(Pw[g * 68 + fk * 8 + tg]);
            af[1] = __float_as_uint(Pw[(g + 8) * 68 + fk * 8 + tg]);
            af[2] = __float_as_uint(Pw[g * 68 + fk * 8 + tg + 4]);
            af[3] = __float_as_uint(Pw[(g + 8) * 68 + fk * 8 + tg + 4]);
#pragma unroll
            for (int fn = 0; fn < 8; fn++) {
                unsigned bf[2];
                bf[0] = __float_as_uint(Vs[(fk * 8 + tg) * 68 + fn * 8 + g]);
                bf[1] = __float_as_uint(Vs[(fk * 8 + tg + 4) * 68 + fn * 8 + g]);
                mma8(of[fn], af, bf);
            }
        }
        __syncwarp();
    }

    l0 += __shfl_xor_sync(0xffffffffu, l0, 1);
    l0 += __shfl_xor_sync(0xffffffffu, l0, 2);
    l1 += __shfl_xor_sync(0xffffffffu, l1, 1);
    l1 += __shfl_xor_sync(0xffffffffu, l1, 2);

    const float i0 = 1.f / fmaxf(l0, 1e-30f), i1 = 1.f / fmaxf(l1, 1e-30f);
    float* cb = ctx + (size_t)(b * S_DIM + qw) * M_DIM + h * HDIM;
#pragma unroll
    for (int fn = 0; fn < 8; fn++) {
        *(float2*)&cb[(size_t)g * M_DIM + fn * 8 + 2 * tg] =
            make_float2(of[fn][0] * i0, of[fn][1] * i0);
        *(float2*)&cb[(size_t)(g + 8) * M_DIM + fn * 8 + 2 * tg] =
            make_float2(of[fn][2] * i1, of[fn][3] * i1);
    }
}

// ------------------------- residual + layernorm ----------------------------
__global__ __launch_bounds__(256)
void ln_kernel(const float* __restrict__ A, const float* __restrict__ R,
               const float* __restrict__ g, const float* __restrict__ be,
               float* __restrict__ out) {
    __shared__ float red[8];
    __shared__ float bcast;
    const int row = blockIdx.x;
    const int tid = threadIdx.x;

    float4 a = ((const float4*)(A + (size_t)row * M_DIM))[tid];
    float4 r = ((const float4*)(R + (size_t)row * M_DIM))[tid];
    float v0 = a.x + r.x, v1 = a.y + r.y, v2 = a.z + r.z, v3 = a.w + r.w;

    float s = v0 + v1 + v2 + v3;
#pragma unroll
    for (int off = 16; off; off >>= 1) s += __shfl_xor_sync(0xffffffffu, s, off);
    if ((tid & 31) == 0) red[tid >> 5] = s;
    __syncthreads();
    if (tid == 0) {
        float t = 0.f;
#pragma unroll
        for (int i = 0; i < 8; i++) t += red[i];
        bcast = t * (1.f / M_DIM);
    }
    __syncthreads();
    const float mu = bcast;

    float d0 = v0 - mu, d1 = v1 - mu, d2 = v2 - mu, d3 = v3 - mu;
    float s2 = d0 * d0 + d1 * d1 + d2 * d2 + d3 * d3;
#pragma unroll
    for (int off = 16; off; off >>= 1) s2 += __shfl_xor_sync(0xffffffffu, s2, off);
    __syncthreads();
    if ((tid & 31) == 0) red[tid >> 5] = s2;
    __syncthreads();
    if (tid == 0) {
        float t = 0.f;
#pragma unroll
        for (int i = 0; i < 8; i++) t += red[i];
        bcast = rsqrtf(t * (1.f / M_DIM) + 1e-5f);
    }
    __syncthreads();
    const float rstd = bcast;

    float4 gg = ((const float4*)g)[tid];
    float4 bb = ((const float4*)be)[tid];
    float4 o;
    o.x = d0 * rstd * gg.x + bb.x;
    o.y = d1 * rstd * gg.y + bb.y;
    o.z = d2 * rstd * gg.z + bb.z;
    o.w = d3 * rstd * gg.w + bb.w;
    ((float4*)(out + (size_t)row * M_DIM))[tid] = o;
}

// ---------------------------------------------------------------------------
extern "C" void kernel_launch(void* const* d_in, const int* in_sizes, int n_in,
                              void* d_out, int out_size) {
    const float* x     = (const float*)d_in[0];
    const int*   amask = (const int*)  d_in[1];
    const float* Wq    = (const float*)d_in[2];
    const float* bq    = (const float*)d_in[3];
    const float* Wk    = (const float*)d_in[4];
    const float* bk    = (const float*)d_in[5];
    const float* Wv    = (const float*)d_in[6];
    const float* bv    = (const float*)d_in[7];
    const float* Wo    = (const float*)d_in[8];
    const float* bo    = (const float*)d_in[9];
    const float* g1    = (const float*)d_in[10];
    const float* b1    = (const float*)d_in[11];
    const float* W1    = (const float*)d_in[12];
    const float* bias1 = (const float*)d_in[13];
    const float* W2    = (const float*)d_in[14];
    const float* bias2 = (const float*)d_in[15];
    const float* g2    = (const float*)d_in[16];
    const float* b2    = (const float*)d_in[17];
    float* out = (float*)d_out;

    float *Wqkv, *bqkv, *qkv, *ctx, *attnproj, *y, *ffh, *ffo;
    cudaGetSymbolAddress((void**)&Wqkv,     g_Wqkv);
    cudaGetSymbolAddress((void**)&bqkv,     g_bqkv);
    cudaGetSymbolAddress((void**)&qkv,      g_qkv);
    cudaGetSymbolAddress((void**)&ctx,      g_ctx);
    cudaGetSymbolAddress((void**)&attnproj, g_attnproj);
    cudaGetSymbolAddress((void**)&y,        g_y);
    cudaGetSymbolAddress((void**)&ffh,      g_ffh);
    cudaGetSymbolAddress((void**)&ffo,      g_ffo);

    const int gemm_smem = 2 * (1536 + 1088) * sizeof(unsigned);    // 20992
    const int attn_smem = (2 * 64 * 68 + 8 * 16 * 68 + 64) * sizeof(float); // 69888
    cudaFuncSetAttribute(gemm_tc<false>, cudaFuncAttributeMaxDynamicSharedMemorySize, gemm_smem);
    cudaFuncSetAttribute(gemm_tc<true>,  cudaFuncAttributeMaxDynamicSharedMemorySize, gemm_smem);
    cudaFuncSetAttribute(attn_tc, cudaFuncAttributeMaxDynamicSharedMemorySize, attn_smem);

    // 1) pack per-head QKV weights
    pack_qkv_kernel<<<(M_DIM * QKV_N + 255) / 256, 256>>>(Wq, Wk, Wv, bq, bk, bv);

    // 2) fused QKV projection
    gemm_tc<false><<<dim3(QKV_N / 128, TOK / 128), 256, gemm_smem>>>(
        x, Wqkv, bqkv, qkv, TOK, QKV_N, M_DIM);

    // 3) attention
    attn_tc<<<dim3(S_DIM / 128, B_DIM * NHEAD), 256, attn_smem>>>(qkv, amask, ctx);

    // 4) output projection
    gemm_tc<false><<<dim3(M_DIM / 128, TOK / 128), 256, gemm_smem>>>(
        ctx, Wo, bo, attnproj, TOK, M_DIM, M_DIM);

    // 5) y = LN(attnproj + x)
    ln_kernel<<<TOK, 256>>>(attnproj, x, g1, b1, y);

    // 6) ffh = relu(y @ W1 + bias1)
    gemm_tc<true><<<dim3(FFN_H / 128, TOK / 128), 256, gemm_smem>>>(
        y, W1, bias1, ffh, TOK, FFN_H, M_DIM);

    // 7) ffo = ffh @ W2 + bias2
    gemm_tc<false><<<dim3(M_DIM / 128, TOK / 128), 256, gemm_smem>>>(
        ffh, W2, bias2, ffo, TOK, M_DIM, FFN_H);

    // 8) out = LN(y + ffo)
    ln_kernel<<<TOK, 256>>>(ffo, y, g2, b2, out);
}

// round 10
// speedup vs baseline: 1.3568x; 1.3568x over previous
#include <cuda_runtime.h>
#include <stdint.h>
#include <math.h>

#define B_DIM 2
#define S_DIM 2048
#define M_DIM 1024
#define NHEAD 16
#define HDIM 64
#define FFN_H 2048
#define TOK (B_DIM * S_DIM)          // 4096
#define QKV_N (3 * M_DIM)            // 3072
#define NEGV -1e9f

// ------------------------- scratch (static device) -------------------------
__device__ float g_Wqkv[M_DIM * QKV_N];        // packed [K=1024, N=3072]
__device__ float g_bqkv[QKV_N];
__device__ float g_qkv[TOK * QKV_N];
__device__ float g_ctx[TOK * M_DIM];
__device__ float g_attnproj[TOK * M_DIM];
__device__ float g_y[TOK * M_DIM];
__device__ float g_ffh[TOK * FFN_H];
__device__ float g_ffo[TOK * M_DIM];

// ------------------------- helpers ------------------------------------
__device__ __forceinline__ float tf32r(float x) {
    unsigned r; asm("cvt.rna.tf32.f32 %0, %1;" : "=r"(r) : "f"(x));
    return __uint_as_float(r);
}
__device__ __forceinline__ void mma8(float* c, const unsigned* a, const unsigned* b) {
    asm volatile(
        "mma.sync.aligned.m16n8k8.row.col.f32.tf32.tf32.f32 "
        "{%0,%1,%2,%3},{%4,%5,%6,%7},{%8,%9},{%0,%1,%2,%3};"
        : "+f"(c[0]), "+f"(c[1]), "+f"(c[2]), "+f"(c[3])
        : "r"(a[0]), "r"(a[1]), "r"(a[2]), "r"(a[3]), "r"(b[0]), "r"(b[1]));
}
__device__ __forceinline__ void cp16(uint32_t dst, const void* src) {
    asm volatile("cp.async.cg.shared.global [%0], [%1], 16;\n" :: "r"(dst), "l"(src));
}
#define CP_COMMIT() asm volatile("cp.async.commit_group;\n" ::: "memory")
#define CP_WAIT(n)  asm volatile("cp.async.wait_group %0;\n" :: "n"(n) : "memory")

// ------------------------- weight repack -----------------------------------
__global__ void pack_qkv_kernel(const float* __restrict__ Wq,
                                const float* __restrict__ Wk,
                                const float* __restrict__ Wv,
                                const float* __restrict__ bq,
                                const float* __restrict__ bk,
                                const float* __restrict__ bv) {
    int idx = blockIdx.x * blockDim.x + threadIdx.x;
    if (idx < M_DIM * QKV_N) {
        int n = idx % QKV_N;
        int k = idx / QKV_N;
        int which = n / M_DIM;
        int hd = n % M_DIM;
        int h = hd / HDIM, d = hd % HDIM;
        const float* W = (which == 0) ? Wq : (which == 1) ? Wk : Wv;
        g_Wqkv[idx] = W[((size_t)h * M_DIM + k) * HDIM + d];
    }
    if (idx < QKV_N) {
        int which = idx / M_DIM;
        int hd = idx % M_DIM;
        const float* bb = (which == 0) ? bq : (which == 1) ? bk : bv;
        g_bqkv[idx] = bb[hd];
    }
}

// ------------------------- tf32 tensor-core GEMM ---------------------------
// 4-stage cp.async pipeline, ONE __syncthreads per k-step.
// C[M,N] = A[M,K]@B[K,N] + bias, optional ReLU. Tile 128x128, K-step 16,
// 256 thr = 8 warps (2x4), warp tile 64x32.
// SMEM: As[4][128][20] | Bs[4][16][136] = 75776 B dynamic. 2 CTA/SM.
template <bool RELU>
__global__ __launch_bounds__(256, 2)
void gemm_tc(const float* __restrict__ A, const float* __restrict__ Bm,
             const float* __restrict__ bias, float* __restrict__ C,
             int M, int N, int K) {
    extern __shared__ float smdyn[];
    float* As = smdyn;                 // 4 * 2560
    float* Bs = smdyn + 4 * 2560;      // 4 * 2176

    const int tid = threadIdx.x, lane = tid & 31, w = tid >> 5;
    const int wm = w >> 2, wn = w & 3;
    const int g = lane >> 2, tg = lane & 3;
    const int row0 = blockIdx.y * 128, col0 = blockIdx.x * 128;

    const int ar = tid >> 2, ac = (tid & 3) * 4;     // A rows ar, ar+64
    const int br = tid >> 5, bc = (tid & 31) * 4;    // B rows br, br+8

    const float* Ap0 = A + (size_t)(row0 + ar) * K + ac;
    const float* Ap1 = Ap0 + (size_t)64 * K;
    const float* Bp  = Bm + col0 + bc;

    uint32_t smA = (uint32_t)__cvta_generic_to_shared(As);
    uint32_t smB = (uint32_t)__cvta_generic_to_shared(Bs);
    const uint32_t dA0 = smA + (ar * 20 + ac) * 4;
    const uint32_t dA1 = dA0 + 64 * 20 * 4;
    const uint32_t dB0 = smB + (br * 136 + bc) * 4;
    const uint32_t dB1 = dB0 + 8 * 136 * 4;

    float acc[4][4][4];
#pragma unroll
    for (int i = 0; i < 4; i++)
#pragma unroll
        for (int j = 0; j < 4; j++)
#pragma unroll
            for (int q = 0; q < 4; q++) acc[i][j][q] = 0.f;

    const int T = K >> 4;

    auto issue = [&](int s, int k0) {
        const uint32_t oa = s * 2560 * 4, ob = s * 2176 * 4;
        cp16(dA0 + oa, Ap0 + k0);
        cp16(dA1 + oa, Ap1 + k0);
        cp16(dB0 + ob, Bp + (size_t)(k0 + br) * N);
        cp16(dB1 + ob, Bp + (size_t)(k0 + br + 8) * N);
        CP_COMMIT();
    };

    issue(0, 0);
    issue(1, 16);
    issue(2, 32);

    for (int t = 0; t < T; t++) {
        CP_WAIT(2);          // stage t's group complete
        __syncthreads();     // data visible to all warps; slot (t-1)%4 reusable

        const int cur = t & 3;
        const float* as = As + cur * 2560;
        const float* bs = Bs + cur * 2176;
#pragma unroll
        for (int fk = 0; fk < 2; fk++) {
            unsigned af[4][4];
#pragma unroll
            for (int mi = 0; mi < 4; mi++) {
                const float* ap = as + (wm * 64 + mi * 16) * 20 + fk * 8;
                af[mi][0] = __float_as_uint(ap[g * 20 + tg]);
                af[mi][1] = __float_as_uint(ap[(g + 8) * 20 + tg]);
                af[mi][2] = __float_as_uint(ap[g * 20 + tg + 4]);
                af[mi][3] = __float_as_uint(ap[(g + 8) * 20 + tg + 4]);
            }
#pragma unroll
            for (int ni = 0; ni < 4; ni++) {
                unsigned bf[2];
                const int ncol = wn * 32 + ni * 8 + g;
                bf[0] = __float_as_uint(bs[(fk * 8 + tg) * 136 + ncol]);
                bf[1] = __float_as_uint(bs[(fk * 8 + tg + 4) * 136 + ncol]);
#pragma unroll
                for (int mi = 0; mi < 4; mi++) mma8(acc[mi][ni], af[mi], bf);
            }
        }

        if (t + 3 < T) issue((t + 3) & 3, (t + 3) * 16);
        else           CP_COMMIT();      // keep group counting uniform
    }

    // epilogue
#pragma unroll
    for (int mi = 0; mi < 4; mi++) {
        const int r = row0 + wm * 64 + mi * 16 + g;
#pragma unroll
        for (int ni = 0; ni < 4; ni++) {
            const int c = col0 + wn * 32 + ni * 8 + 2 * tg;
            const float b0 = bias[c], b1 = bias[c + 1];
            float v0 = acc[mi][ni][0] + b0, v1 = acc[mi][ni][1] + b1;
            float v2 = acc[mi][ni][2] + b0, v3 = acc[mi][ni][3] + b1;
            if (RELU) {
                v0 = fmaxf(v0, 0.f); v1 = fmaxf(v1, 0.f);
                v2 = fmaxf(v2, 0.f); v3 = fmaxf(v3, 0.f);
            }
            *(float2*)&C[(size_t)r * N + c] = make_float2(v0, v1);
            *(float2*)&C[(size_t)(r + 8) * N + c] = make_float2(v2, v3);
        }
    }
}

// ------------------------- tf32 flash attention ----------------------------
// grid (S/128, B*H), 256 thr = 8 warps; warp = 16 queries; key tile 64.
__global__ __launch_bounds__(256, 2)
void attn_tc(const float* __restrict__ qkv, const int* __restrict__ mask,
             float* __restrict__ ctx) {
    extern __shared__ float sm[];
    float* Ks  = sm;                       // [64][68]
    float* Vs  = sm + 64 * 68;             // [64][68]
    float* Pw0 = sm + 2 * 64 * 68;         // [8][16][68]
    float* Ms  = Pw0 + 8 * 16 * 68;        // [64]

    const int tid = threadIdx.x, lane = tid & 31, w = tid >> 5;
    const int g = lane >> 2, tg = lane & 3;
    const int bh = blockIdx.y, b = bh >> 4, h = bh & 15;
    const int qw = blockIdx.x * 128 + w * 16;
    float* Pw = Pw0 + w * 16 * 68;

    unsigned qf[8][4];
    {
        const float* qb = qkv + (size_t)(b * S_DIM + qw) * QKV_N + h * HDIM;
#pragma unroll
        for (int fk = 0; fk < 8; fk++) {
            qf[fk][0] = __float_as_uint(tf32r(qb[(size_t)g * QKV_N + fk * 8 + tg] * 0.125f));
            qf[fk][1] = __float_as_uint(tf32r(qb[(size_t)(g + 8) * QKV_N + fk * 8 + tg] * 0.125f));
            qf[fk][2] = __float_as_uint(tf32r(qb[(size_t)g * QKV_N + fk * 8 + tg + 4] * 0.125f));
            qf[fk][3] = __float_as_uint(tf32r(qb[(size_t)(g + 8) * QKV_N + fk * 8 + tg + 4] * 0.125f));
        }
    }

    float of[8][4];
#pragma unroll
    for (int i = 0; i < 8; i++) { of[i][0] = of[i][1] = of[i][2] = of[i][3] = 0.f; }
    float m0 = -INFINITY, m1 = -INFINITY, l0 = 0.f, l1 = 0.f;

    const int kr = tid >> 4, kc = (tid & 15) * 4;

    for (int kt = 0; kt < S_DIM; kt += 64) {
        __syncthreads();
#pragma unroll
        for (int i = 0; i < 4; i++) {
            const int r = kr + i * 16;
            const float* kb = qkv + (size_t)(b * S_DIM + kt + r) * QKV_N + M_DIM + h * HDIM + kc;
            float4 kv = *(const float4*)kb;
            float4 vv = *(const float4*)(kb + M_DIM);
            float* kd = &Ks[r * 68 + kc];
            kd[0] = tf32r(kv.x); kd[1] = tf32r(kv.y);
            kd[2] = tf32r(kv.z); kd[3] = tf32r(kv.w);
            float* vd = &Vs[r * 68 + kc];
            vd[0] = tf32r(vv.x); vd[1] = tf32r(vv.y);
            vd[2] = tf32r(vv.z); vd[3] = tf32r(vv.w);
        }
        if (tid < 64) Ms[tid] = mask[b * S_DIM + kt + tid] ? 0.f : NEGV;
        __syncthreads();

        float s[8][4];
#pragma unroll
        for (int fn = 0; fn < 8; fn++) { s[fn][0] = s[fn][1] = s[fn][2] = s[fn][3] = 0.f; }
#pragma unroll
        for (int fk = 0; fk < 8; fk++) {
#pragma unroll
            for (int fn = 0; fn < 8; fn++) {
                unsigned bf[2];
                bf[0] = __float_as_uint(Ks[(fn * 8 + g) * 68 + fk * 8 + tg]);
                bf[1] = __float_as_uint(Ks[(fn * 8 + g) * 68 + fk * 8 + tg + 4]);
                mma8(s[fn], qf[fk], bf);
            }
        }

        float mx0 = -INFINITY, mx1 = -INFINITY;
#pragma unroll
        for (int fn = 0; fn < 8; fn++) {
            const float mk0 = Ms[fn * 8 + 2 * tg], mk1 = Ms[fn * 8 + 2 * tg + 1];
            s[fn][0] += mk0; s[fn][1] += mk1;
            s[fn][2] += mk0; s[fn][3] += mk1;
            mx0 = fmaxf(mx0, fmaxf(s[fn][0], s[fn][1]));
            mx1 = fmaxf(mx1, fmaxf(s[fn][2], s[fn][3]));
        }
        mx0 = fmaxf(mx0, __shfl_xor_sync(0xffffffffu, mx0, 1));
        mx0 = fmaxf(mx0, __shfl_xor_sync(0xffffffffu, mx0, 2));
        mx1 = fmaxf(mx1, __shfl_xor_sync(0xffffffffu, mx1, 1));
        mx1 = fmaxf(mx1, __shfl_xor_sync(0xffffffffu, mx1, 2));
        const float nm0 = fmaxf(m0, mx0), nm1 = fmaxf(m1, mx1);
        const float a0 = __expf(m0 - nm0), a1 = __expf(m1 - nm1);
        m0 = nm0; m1 = nm1;
        l0 *= a0; l1 *= a1;
#pragma unroll
        for (int fn = 0; fn < 8; fn++) {
            of[fn][0] *= a0; of[fn][1] *= a0;
            of[fn][2] *= a1; of[fn][3] *= a1;
            float p0 = tf32r(__expf(s[fn][0] - m0));
            float p1 = tf32r(__expf(s[fn][1] - m0));
            float p2 = tf32r(__expf(s[fn][2] - m1));
            float p3 = tf32r(__expf(s[fn][3] - m1));
            l0 += p0 + p1; l1 += p2 + p3;
            *(float2*)&Pw[g * 68 + fn * 8 + 2 * tg] = make_float2(p0, p1);
            *(float2*)&Pw[(g + 8) * 68 + fn * 8 + 2 * tg] = make_float2(p2, p3);
        }
        __syncwarp();

#pragma unroll
        for (int fk = 0; fk < 8; fk++) {
            unsigned af[4];
            af[0] = __float_as_uint(Pw[g * 68 + fk * 8 + tg]);
            af[1] = __float_as_uint(Pw[(g + 8) * 68 + fk * 8 + tg]);
            af[2] = __float_as_uint(Pw[g * 68 + fk * 8 + tg + 4]);
            af[3] = __float_as_uint(Pw[(g + 8) * 68 + fk * 8 + tg + 4]);
#pragma unroll
            for (int fn = 0; fn < 8; fn++) {
                unsigned bf[2];
                bf[0] = __float_as_uint(Vs[(fk * 8 + tg) * 68 + fn * 8 + g]);
                bf[1] = __float_as_uint(Vs[(fk * 8 + tg + 4) * 68 + fn * 8 + g]);
                mma8(of[fn], af, bf);
            }
        }
        __syncwarp();
    }

    l0 += __shfl_xor_sync(0xffffffffu, l0, 1);
    l0 += __shfl_xor_sync(0xffffffffu, l0, 2);
    l1 += __shfl_xor_sync(0xffffffffu, l1, 1);
    l1 += __shfl_xor_sync(0xffffffffu, l1, 2);

    const float i0 = 1.f / fmaxf(l0, 1e-30f), i1 = 1.f / fmaxf(l1, 1e-30f);
    float* cb = ctx + (size_t)(b * S_DIM + qw) * M_DIM + h * HDIM;
#pragma unroll
    for (int fn = 0; fn < 8; fn++) {
        *(float2*)&cb[(size_t)g * M_DIM + fn * 8 + 2 * tg] =
            make_float2(of[fn][0] * i0, of[fn][1] * i0);
        *(float2*)&cb[(size_t)(g + 8) * M_DIM + fn * 8 + 2 * tg] =
            make_float2(of[fn][2] * i1, of[fn][3] * i1);
    }
}

// ------------------------- residual + layernorm ----------------------------
__global__ __launch_bounds__(256)
void ln_kernel(const float* __restrict__ A, const float* __restrict__ R,
               const float* __restrict__ g, const float* __restrict__ be,
               float* __restrict__ out) {
    __shared__ float red[8];
    __shared__ float bcast;
    const int row = blockIdx.x;
    const int tid = threadIdx.x;

    float4 a = ((const float4*)(A + (size_t)row * M_DIM))[tid];
    float4 r = ((const float4*)(R + (size_t)row * M_DIM))[tid];
    float v0 = a.x + r.x, v1 = a.y + r.y, v2 = a.z + r.z, v3 = a.w + r.w;

    float s = v0 + v1 + v2 + v3;
#pragma unroll
    for (int off = 16; off; off >>= 1) s += __shfl_xor_sync(0xffffffffu, s, off);
    if ((tid & 31) == 0) red[tid >> 5] = s;
    __syncthreads();
    if (tid == 0) {
        float t = 0.f;
#pragma unroll
        for (int i = 0; i < 8; i++) t += red[i];
        bcast = t * (1.f / M_DIM);
    }
    __syncthreads();
    const float mu = bcast;

    float d0 = v0 - mu, d1 = v1 - mu, d2 = v2 - mu, d3 = v3 - mu;
    float s2 = d0 * d0 + d1 * d1 + d2 * d2 + d3 * d3;
#pragma unroll
    for (int off = 16; off; off >>= 1) s2 += __shfl_xor_sync(0xffffffffu, s2, off);
    __syncthreads();
    if ((tid & 31) == 0) red[tid >> 5] = s2;
    __syncthreads();
    if (tid == 0) {
        float t = 0.f;
#pragma unroll
        for (int i = 0; i < 8; i++) t += red[i];
        bcast = rsqrtf(t * (1.f / M_DIM) + 1e-5f);
    }
    __syncthreads();
    const float rstd = bcast;

    float4 gg = ((const float4*)g)[tid];
    float4 bb = ((const float4*)be)[tid];
    float4 o;
    o.x = d0 * rstd * gg.x + bb.x;
    o.y = d1 * rstd * gg.y + bb.y;
    o.z = d2 * rstd * gg.z + bb.z;
    o.w = d3 * rstd * gg.w + bb.w;
    ((float4*)(out + (size_t)row * M_DIM))[tid] = o;
}

// ---------------------------------------------------------------------------
extern "C" void kernel_launch(void* const* d_in, const int* in_sizes, int n_in,
                              void* d_out, int out_size) {
    const float* x     = (const float*)d_in[0];
    const int*   amask = (const int*)  d_in[1];
    const float* Wq    = (const float*)d_in[2];
    const float* bq    = (const float*)d_in[3];
    const float* Wk    = (const float*)d_in[4];
    const float* bk    = (const float*)d_in[5];
    const float* Wv    = (const float*)d_in[6];
    const float* bv    = (const float*)d_in[7];
    const float* Wo    = (const float*)d_in[8];
    const float* bo    = (const float*)d_in[9];
    const float* g1    = (const float*)d_in[10];
    const float* b1    = (const float*)d_in[11];
    const float* W1    = (const float*)d_in[12];
    const float* bias1 = (const float*)d_in[13];
    const float* W2    = (const float*)d_in[14];
    const float* bias2 = (const float*)d_in[15];
    const float* g2    = (const float*)d_in[16];
    const float* b2    = (const float*)d_in[17];
    float* out = (float*)d_out;

    float *Wqkv, *bqkv, *qkv, *ctx, *attnproj, *y, *ffh, *ffo;
    cudaGetSymbolAddress((void**)&Wqkv,     g_Wqkv);
    cudaGetSymbolAddress((void**)&bqkv,     g_bqkv);
    cudaGetSymbolAddress((void**)&qkv,      g_qkv);
    cudaGetSymbolAddress((void**)&ctx,      g_ctx);
    cudaGetSymbolAddress((void**)&attnproj, g_attnproj);
    cudaGetSymbolAddress((void**)&y,        g_y);
    cudaGetSymbolAddress((void**)&ffh,      g_ffh);
    cudaGetSymbolAddress((void**)&ffo,      g_ffo);

    const int gemm_smem = 4 * (2560 + 2176) * sizeof(float);       // 75776
    const int attn_smem = (2 * 64 * 68 + 8 * 16 * 68 + 64) * sizeof(float); // 69888
    cudaFuncSetAttribute(gemm_tc<false>, cudaFuncAttributeMaxDynamicSharedMemorySize, gemm_smem);
    cudaFuncSetAttribute(gemm_tc<true>,  cudaFuncAttributeMaxDynamicSharedMemorySize, gemm_smem);
    cudaFuncSetAttribute(attn_tc, cudaFuncAttributeMaxDynamicSharedMemorySize, attn_smem);

    // 1) pack per-head QKV weights
    pack_qkv_kernel<<<(M_DIM * QKV_N + 255) / 256, 256>>>(Wq, Wk, Wv, bq, bk, bv);

    // 2) fused QKV projection
    gemm_tc<false><<<dim3(QKV_N / 128, TOK / 128), 256, gemm_smem>>>(
        x, Wqkv, bqkv, qkv, TOK, QKV_N, M_DIM);

    // 3) attention
    attn_tc<<<dim3(S_DIM / 128, B_DIM * NHEAD), 256, attn_smem>>>(qkv, amask, ctx);

    // 4) output projection
    gemm_tc<false><<<dim3(M_DIM / 128, TOK / 128), 256, gemm_smem>>>(
        ctx, Wo, bo, attnproj, TOK, M_DIM, M_DIM);

    // 5) y = LN(attnproj + x)
    ln_kernel<<<TOK, 256>>>(attnproj, x, g1, b1, y);

    // 6) ffh = relu(y @ W1 + bias1)
    gemm_tc<true><<<dim3(FFN_H / 128, TOK / 128), 256, gemm_smem>>>(
        y, W1, bias1, ffh, TOK, FFN_H, M_DIM);

    // 7) ffo = ffh @ W2 + bias2
    gemm_tc<false><<<dim3(M_DIM / 128, TOK / 128), 256, gemm_smem>>>(
        ffh, W2, bias2, ffo, TOK, M_DIM, FFN_H);

    // 8) out = LN(y + ffo)
    ln_kernel<<<TOK, 256>>>(ffo, y, g2, b2, out);
}

// round 11
// speedup vs baseline: 1.6007x; 1.1798x over previous
#include <cuda_runtime.h>
#include <cuda_fp16.h>
#include <stdint.h>
#include <math.h>

#define B_DIM 2
#define S_DIM 2048
#define M_DIM 1024
#define NHEAD 16
#define HDIM 64
#define FFN_H 2048
#define TOK (B_DIM * S_DIM)          // 4096
#define QKV_N (3 * M_DIM)            // 3072
#define NEGV -1e9f

// ------------------------- scratch (static device) -------------------------
__device__ __half g_xh[TOK * M_DIM];           // x in half
__device__ __half g_Wqkvh[QKV_N * M_DIM];      // [n][k] half (transposed)
__device__ __half g_Woh[M_DIM * M_DIM];        // [n][k]
__device__ __half g_W1h[FFN_H * M_DIM];        // [n][k]
__device__ __half g_W2h[M_DIM * FFN_H];        // [n][k]
__device__ float  g_bqkv[QKV_N];
__device__ float  g_qkv[TOK * QKV_N];          // float (attention input)
__device__ __half g_ctxh[TOK * M_DIM];         // attention out, half
__device__ float  g_attnproj[TOK * M_DIM];
__device__ float  g_y[TOK * M_DIM];
__device__ __half g_yh[TOK * M_DIM];
__device__ __half g_ffhh[TOK * FFN_H];
__device__ float  g_ffo[TOK * M_DIM];

// ------------------------- helpers ------------------------------------
__device__ __forceinline__ float tf32r(float x) {
    unsigned r; asm("cvt.rna.tf32.f32 %0, %1;" : "=r"(r) : "f"(x));
    return __uint_as_float(r);
}
__device__ __forceinline__ void mma8(float* c, const unsigned* a, const unsigned* b) {
    asm volatile(
        "mma.sync.aligned.m16n8k8.row.col.f32.tf32.tf32.f32 "
        "{%0,%1,%2,%3},{%4,%5,%6,%7},{%8,%9},{%0,%1,%2,%3};"
        : "+f"(c[0]), "+f"(c[1]), "+f"(c[2]), "+f"(c[3])
        : "r"(a[0]), "r"(a[1]), "r"(a[2]), "r"(a[3]), "r"(b[0]), "r"(b[1]));
}
__device__ __forceinline__ void mma16(float* c, const unsigned* a, const unsigned* b) {
    asm volatile(
        "mma.sync.aligned.m16n8k16.row.col.f32.f16.f16.f32 "
        "{%0,%1,%2,%3},{%4,%5,%6,%7},{%8,%9},{%0,%1,%2,%3};"
        : "+f"(c[0]), "+f"(c[1]), "+f"(c[2]), "+f"(c[3])
        : "r"(a[0]), "r"(a[1]), "r"(a[2]), "r"(a[3]), "r"(b[0]), "r"(b[1]));
}
__device__ __forceinline__ void cp16(uint32_t dst, const void* src) {
    asm volatile("cp.async.cg.shared.global [%0], [%1], 16;\n" :: "r"(dst), "l"(src));
}
#define CP_COMMIT() asm volatile("cp.async.commit_group;\n" ::: "memory")
#define CP_WAIT(n)  asm volatile("cp.async.wait_group %0;\n" :: "n"(n) : "memory")

// ------------------------- pack kernels -------------------------------------
__global__ void pack_xh(const float* __restrict__ x) {
    int i = (blockIdx.x * blockDim.x + threadIdx.x) * 4;
    float4 v = *(const float4*)&x[i];
    __half2* d = (__half2*)&g_xh[i];
    d[0] = __floats2half2_rn(v.x, v.y);
    d[1] = __floats2half2_rn(v.z, v.w);
}
__global__ void pack_bias(const float* __restrict__ bq, const float* __restrict__ bk,
                          const float* __restrict__ bv) {
    int idx = blockIdx.x * blockDim.x + threadIdx.x;
    if (idx < QKV_N) {
        int which = idx / M_DIM, hd = idx % M_DIM;
        const float* bb = (which == 0) ? bq : (which == 1) ? bk : bv;
        g_bqkv[idx] = bb[hd];
    }
}
// Wq/Wk/Wv [H][K][D] -> g_Wqkvh[n][k] half, n = which*1024 + h*64 + d
__global__ void pack_qkvT(const float* __restrict__ Wq, const float* __restrict__ Wk,
                          const float* __restrict__ Wv) {
    __shared__ float t[32][33];
    const int k0 = blockIdx.x * 32, n0 = blockIdx.y * 32;
    const int which = n0 >> 10, hd0 = n0 & 1023, h = hd0 >> 6, d0 = hd0 & 63;
    const float* W = (which == 0) ? Wq : (which == 1) ? Wk : Wv;
    const int tx = threadIdx.x, ty = threadIdx.y;
#pragma unroll
    for (int yy = ty; yy < 32; yy += 8)
        t[yy][tx] = W[((size_t)(h << 10) + k0 + yy) * 64 + d0 + tx];
    __syncthreads();
#pragma unroll
    for (int yy = ty; yy < 32; yy += 8)
        g_Wqkvh[(size_t)(n0 + yy) * M_DIM + k0 + tx] = __float2half_rn(t[tx][yy]);
}
// src [K][N] row-major -> dst[n][k] half
__global__ void packT(const float* __restrict__ src, __half* __restrict__ dst,
                      int K, int N) {
    __shared__ float t[32][33];
    const int k0 = blockIdx.x * 32, n0 = blockIdx.y * 32;
    const int tx = threadIdx.x, ty = threadIdx.y;
#pragma unroll
    for (int yy = ty; yy < 32; yy += 8)
        t[yy][tx] = src[(size_t)(k0 + yy) * N + n0 + tx];
    __syncthreads();
#pragma unroll
    for (int yy = ty; yy < 32; yy += 8)
        dst[(size_t)(n0 + yy) * K + k0 + tx] = __float2half_rn(t[tx][yy]);
}

// ------------------------- fp16 tensor-core GEMM (cp.async 4-stage) --------
// C = A[M,K] @ Bt[N,K]^T + bias, fp32 accum. Optional ReLU.
// A [M][K] half row-major, Bt [N][K] half (pre-transposed weights).
// Tile 128x128, K-step 16, 256 thr (8 warps 2x4), warp tile 64x32.
// SMEM words: As[4][128][12] | Bs[4][128][12]  (k-pairs as 32-bit words).
template <bool RELU, bool WF, bool WH>
__global__ __launch_bounds__(256, 2)
void gemm_h(const __half* __restrict__ A, const __half* __restrict__ Bt,
            const float* __restrict__ bias, float* __restrict__ Cf,
            __half* __restrict__ Ch, int M, int N, int K) {
    extern __shared__ unsigned smw[];
    unsigned* As = smw;                 // 4 * 1536
    unsigned* Bs = smw + 4 * 1536;      // 4 * 1536

    const int tid = threadIdx.x, lane = tid & 31, w = tid >> 5;
    const int wm = w >> 2, wn = w & 3;
    const int g = lane >> 2, tg = lane & 3;
    const int row0 = blockIdx.y * 128, col0 = blockIdx.x * 128;

    const int r = tid >> 1, sel = tid & 1;     // row + 8-half chunk
    const __half* Agp = A + (size_t)(row0 + r) * K + sel * 8;
    const __half* Bgp = Bt + (size_t)(col0 + r) * K + sel * 8;

    uint32_t smA = (uint32_t)__cvta_generic_to_shared(As);
    uint32_t smB = (uint32_t)__cvta_generic_to_shared(Bs);
    const uint32_t dA = smA + (r * 12 + sel * 4) * 4;
    const uint32_t dB = smB + (r * 12 + sel * 4) * 4;

    float acc[4][4][4];
#pragma unroll
    for (int i = 0; i < 4; i++)
#pragma unroll
        for (int j = 0; j < 4; j++)
#pragma unroll
            for (int q = 0; q < 4; q++) acc[i][j][q] = 0.f;

    const int T = K >> 4;

    auto issue = [&](int s, int k0) {
        cp16(dA + s * 6144, Agp + k0);
        cp16(dB + s * 6144, Bgp + k0);
        CP_COMMIT();
    };

    issue(0, 0);
    issue(1, 16);
    issue(2, 32);

    for (int t = 0; t < T; t++) {
        CP_WAIT(2);
        __syncthreads();

        const int cur = t & 3;
        const unsigned* as = As + cur * 1536;
        const unsigned* bs = Bs + cur * 1536;

        unsigned af[4][4];
#pragma unroll
        for (int mi = 0; mi < 4; mi++) {
            const unsigned* ap = as + (wm * 64 + mi * 16) * 12;
            af[mi][0] = ap[g * 12 + tg];
            af[mi][1] = ap[(g + 8) * 12 + tg];
            af[mi][2] = ap[g * 12 + tg + 4];
            af[mi][3] = ap[(g + 8) * 12 + tg + 4];
        }
#pragma unroll
        for (int ni = 0; ni < 4; ni++) {
            const unsigned* bw = bs + (wn * 32 + ni * 8 + g) * 12;
            unsigned bf[2];
            bf[0] = bw[tg];
            bf[1] = bw[tg + 4];
#pragma unroll
            for (int mi = 0; mi < 4; mi++) mma16(acc[mi][ni], af[mi], bf);
        }

        if (t + 3 < T) issue((t + 3) & 3, (t + 3) * 16);
        else           CP_COMMIT();
    }

    // epilogue
#pragma unroll
    for (int mi = 0; mi < 4; mi++) {
        const int rr = row0 + wm * 64 + mi * 16 + g;
#pragma unroll
        for (int ni = 0; ni < 4; ni++) {
            const int c = col0 + wn * 32 + ni * 8 + 2 * tg;
            const float b0 = bias[c], b1 = bias[c + 1];
            float v0 = acc[mi][ni][0] + b0, v1 = acc[mi][ni][1] + b1;
            float v2 = acc[mi][ni][2] + b0, v3 = acc[mi][ni][3] + b1;
            if (RELU) {
                v0 = fmaxf(v0, 0.f); v1 = fmaxf(v1, 0.f);
                v2 = fmaxf(v2, 0.f); v3 = fmaxf(v3, 0.f);
            }
            if (WF) {
                *(float2*)&Cf[(size_t)rr * N + c] = make_float2(v0, v1);
                *(float2*)&Cf[(size_t)(rr + 8) * N + c] = make_float2(v2, v3);
            }
            if (WH) {
                *(__half2*)&Ch[(size_t)rr * N + c] = __floats2half2_rn(v0, v1);
                *(__half2*)&Ch[(size_t)(rr + 8) * N + c] = __floats2half2_rn(v2, v3);
            }
        }
    }
}

// ------------------------- tf32 flash attention (r10, half ctx out) --------
__global__ __launch_bounds__(256, 2)
void attn_tc(const float* __restrict__ qkv, const int* __restrict__ mask,
             __half* __restrict__ ctx) {
    extern __shared__ float sm[];
    float* Ks  = sm;                       // [64][68]
    float* Vs  = sm + 64 * 68;             // [64][68]
    float* Pw0 = sm + 2 * 64 * 68;         // [8][16][68]
    float* Ms  = Pw0 + 8 * 16 * 68;        // [64]

    const int tid = threadIdx.x, lane = tid & 31, w = tid >> 5;
    const int g = lane >> 2, tg = lane & 3;
    const int bh = blockIdx.y, b = bh >> 4, h = bh & 15;
    const int qw = blockIdx.x * 128 + w * 16;
    float* Pw = Pw0 + w * 16 * 68;

    unsigned qf[8][4];
    {
        const float* qb = qkv + (size_t)(b * S_DIM + qw) * QKV_N + h * HDIM;
#pragma unroll
        for (int fk = 0; fk < 8; fk++) {
            qf[fk][0] = __float_as_uint(tf32r(qb[(size_t)g * QKV_N + fk * 8 + tg] * 0.125f));
            qf[fk][1] = __float_as_uint(tf32r(qb[(size_t)(g + 8) * QKV_N + fk * 8 + tg] * 0.125f));
            qf[fk][2] = __float_as_uint(tf32r(qb[(size_t)g * QKV_N + fk * 8 + tg + 4] * 0.125f));
            qf[fk][3] = __float_as_uint(tf32r(qb[(size_t)(g + 8) * QKV_N + fk * 8 + tg + 4] * 0.125f));
        }
    }

    float of[8][4];
#pragma unroll
    for (int i = 0; i < 8; i++) { of[i][0] = of[i][1] = of[i][2] = of[i][3] = 0.f; }
    float m0 = -INFINITY, m1 = -INFINITY, l0 = 0.f, l1 = 0.f;

    const int kr = tid >> 4, kc = (tid & 15) * 4;

    for (int kt = 0; kt < S_DIM; kt += 64) {
        __syncthreads();
#pragma unroll
        for (int i = 0; i < 4; i++) {
            const int rr = kr + i * 16;
            const float* kb = qkv + (size_t)(b * S_DIM + kt + rr) * QKV_N + M_DIM + h * HDIM + kc;
            float4 kv = *(const float4*)kb;
            float4 vv = *(const float4*)(kb + M_DIM);
            float* kd = &Ks[rr * 68 + kc];
            kd[0] = tf32r(kv.x); kd[1] = tf32r(kv.y);
            kd[2] = tf32r(kv.z); kd[3] = tf32r(kv.w);
            float* vd = &Vs[rr * 68 + kc];
            vd[0] = tf32r(vv.x); vd[1] = tf32r(vv.y);
            vd[2] = tf32r(vv.z); vd[3] = tf32r(vv.w);
        }
        if (tid < 64) Ms[tid] = mask[b * S_DIM + kt + tid] ? 0.f : NEGV;
        __syncthreads();

        float s[8][4];
#pragma unroll
        for (int fn = 0; fn < 8; fn++) { s[fn][0] = s[fn][1] = s[fn][2] = s[fn][3] = 0.f; }
#pragma unroll
        for (int fk = 0; fk < 8; fk++) {
#pragma unroll
            for (int fn = 0; fn < 8; fn++) {
                unsigned bf[2];
                bf[0] = __float_as_uint(Ks[(fn * 8 + g) * 68 + fk * 8 + tg]);
                bf[1] = __float_as_uint(Ks[(fn * 8 + g) * 68 + fk * 8 + tg + 4]);
                mma8(s[fn], qf[fk], bf);
            }
        }

        float mx0 = -INFINITY, mx1 = -INFINITY;
#pragma unroll
        for (int fn = 0; fn < 8; fn++) {
            const float mk0 = Ms[fn * 8 + 2 * tg], mk1 = Ms[fn * 8 + 2 * tg + 1];
            s[fn][0] += mk0; s[fn][1] += mk1;
            s[fn][2] += mk0; s[fn][3] += mk1;
            mx0 = fmaxf(mx0, fmaxf(s[fn][0], s[fn][1]));
            mx1 = fmaxf(mx1, fmaxf(s[fn][2], s[fn][3]));
        }
        mx0 = fmaxf(mx0, __shfl_xor_sync(0xffffffffu, mx0, 1));
        mx0 = fmaxf(mx0, __shfl_xor_sync(0xffffffffu, mx0, 2));
        mx1 = fmaxf(mx1, __shfl_xor_sync(0xffffffffu, mx1, 1));
        mx1 = fmaxf(mx1, __shfl_xor_sync(0xffffffffu, mx1, 2));
        const float nm0 = fmaxf(m0, mx0), nm1 = fmaxf(m1, mx1);
        const float a0 = __expf(m0 - nm0), a1 = __expf(m1 - nm1);
        m0 = nm0; m1 = nm1;
        l0 *= a0; l1 *= a1;
#pragma unroll
        for (int fn = 0; fn < 8; fn++) {
            of[fn][0] *= a0; of[fn][1] *= a0;
            of[fn][2] *= a1; of[fn][3] *= a1;
            float p0 = tf32r(__expf(s[fn][0] - m0));
            float p1 = tf32r(__expf(s[fn][1] - m0));
            float p2 = tf32r(__expf(s[fn][2] - m1));
            float p3 = tf32r(__expf(s[fn][3] - m1));
            l0 += p0 + p1; l1 += p2 + p3;
            *(float2*)&Pw[g * 68 + fn * 8 + 2 * tg] = make_float2(p0, p1);
            *(float2*)&Pw[(g + 8) * 68 + fn * 8 + 2 * tg] = make_float2(p2, p3);
        }
        __syncwarp();

#pragma unroll
        for (int fk = 0; fk < 8; fk++) {
            unsigned af[4];
            af[0] = __float_as_uint(Pw[g * 68 + fk * 8 + tg]);
            af[1] = __float_as_uint(Pw[(g + 8) * 68 + fk * 8 + tg]);
            af[2] = __float_as_uint(Pw[g * 68 + fk * 8 + tg + 4]);
            af[3] = __float_as_uint(Pw[(g + 8) * 68 + fk * 8 + tg + 4]);
#pragma unroll
            for (int fn = 0; fn < 8; fn++) {
                unsigned bf[2];
                bf[0] = __float_as_uint(Vs[(fk * 8 + tg) * 68 + fn * 8 + g]);
                bf[1] = __float_as_uint(Vs[(fk * 8 + tg + 4) * 68 + fn * 8 + g]);
                mma8(of[fn], af, bf);
            }
        }
        __syncwarp();
    }

    l0 += __shfl_xor_sync(0xffffffffu, l0, 1);
    l0 += __shfl_xor_sync(0xffffffffu, l0, 2);
    l1 += __shfl_xor_sync(0xffffffffu, l1, 1);
    l1 += __shfl_xor_sync(0xffffffffu, l1, 2);

    const float i0 = 1.f / fmaxf(l0, 1e-30f), i1 = 1.f / fmaxf(l1, 1e-30f);
    __half* cb = ctx + (size_t)(b * S_DIM + qw) * M_DIM + h * HDIM;
#pragma unroll
    for (int fn = 0; fn < 8; fn++) {
        *(__half2*)&cb[(size_t)g * M_DIM + fn * 8 + 2 * tg] =
            __floats2half2_rn(of[fn][0] * i0, of[fn][1] * i0);
        *(__half2*)&cb[(size_t)(g + 8) * M_DIM + fn * 8 + 2 * tg] =
            __floats2half2_rn(of[fn][2] * i1, of[fn][3] * i1);
    }
}

// ------------------------- residual + layernorm ----------------------------
template <bool WH>
__global__ __launch_bounds__(256)
void ln_kernel(const float* __restrict__ A, const float* __restrict__ R,
               const float* __restrict__ g, const float* __restrict__ be,
               float* __restrict__ out, __half* __restrict__ outh) {
    __shared__ float red[8];
    __shared__ float bcast;
    const int row = blockIdx.x;
    const int tid = threadIdx.x;

    float4 a = ((const float4*)(A + (size_t)row * M_DIM))[tid];
    float4 r = ((const float4*)(R + (size_t)row * M_DIM))[tid];
    float v0 = a.x + r.x, v1 = a.y + r.y, v2 = a.z + r.z, v3 = a.w + r.w;

    float s = v0 + v1 + v2 + v3;
#pragma unroll
    for (int off = 16; off; off >>= 1) s += __shfl_xor_sync(0xffffffffu, s, off);
    if ((tid & 31) == 0) red[tid >> 5] = s;
    __syncthreads();
    if (tid == 0) {
        float t = 0.f;
#pragma unroll
        for (int i = 0; i < 8; i++) t += red[i];
        bcast = t * (1.f / M_DIM);
    }
    __syncthreads();
    const float mu = bcast;

    float d0 = v0 - mu, d1 = v1 - mu, d2 = v2 - mu, d3 = v3 - mu;
    float s2 = d0 * d0 + d1 * d1 + d2 * d2 + d3 * d3;
#pragma unroll
    for (int off = 16; off; off >>= 1) s2 += __shfl_xor_sync(0xffffffffu, s2, off);
    __syncthreads();
    if ((tid & 31) == 0) red[tid >> 5] = s2;
    __syncthreads();
    if (tid == 0) {
        float t = 0.f;
#pragma unroll
        for (int i = 0; i < 8; i++) t += red[i];
        bcast = rsqrtf(t * (1.f / M_DIM) + 1e-5f);
    }
    __syncthreads();
    const float rstd = bcast;

    float4 gg = ((const float4*)g)[tid];
    float4 bb = ((const float4*)be)[tid];
    float4 o;
    o.x = d0 * rstd * gg.x + bb.x;
    o.y = d1 * rstd * gg.y + bb.y;
    o.z = d2 * rstd * gg.z + bb.z;
    o.w = d3 * rstd * gg.w + bb.w;
    ((float4*)(out + (size_t)row * M_DIM))[tid] = o;
    if (WH) {
        __half2* hd = (__half2*)&outh[(size_t)row * M_DIM + tid * 4];
        hd[0] = __floats2half2_rn(o.x, o.y);
        hd[1] = __floats2half2_rn(o.z, o.w);
    }
}

// ---------------------------------------------------------------------------
extern "C" void kernel_launch(void* const* d_in, const int* in_sizes, int n_in,
                              void* d_out, int out_size) {
    const float* x     = (const float*)d_in[0];
    const int*   amask = (const int*)  d_in[1];
    const float* Wq    = (const float*)d_in[2];
    const float* bq    = (const float*)d_in[3];
    const float* Wk    = (const float*)d_in[4];
    const float* bk    = (const float*)d_in[5];
    const float* Wv    = (const float*)d_in[6];
    const float* bv    = (const float*)d_in[7];
    const float* Wo    = (const float*)d_in[8];
    const float* bo    = (const float*)d_in[9];
    const float* g1    = (const float*)d_in[10];
    const float* b1    = (const float*)d_in[11];
    const float* W1    = (const float*)d_in[12];
    const float* bias1 = (const float*)d_in[13];
    const float* W2    = (const float*)d_in[14];
    const float* bias2 = (const float*)d_in[15];
    const float* g2    = (const float*)d_in[16];
    const float* b2    = (const float*)d_in[17];
    float* out = (float*)d_out;

    __half *xh, *Wqkvh, *Woh, *W1h, *W2h, *ctxh, *yh, *ffhh;
    float *bqkv, *qkv, *attnproj, *y, *ffo;
    cudaGetSymbolAddress((void**)&xh,       g_xh);
    cudaGetSymbolAddress((void**)&Wqkvh,    g_Wqkvh);
    cudaGetSymbolAddress((void**)&Woh,      g_Woh);
    cudaGetSymbolAddress((void**)&W1h,      g_W1h);
    cudaGetSymbolAddress((void**)&W2h,      g_W2h);
    cudaGetSymbolAddress((void**)&bqkv,     g_bqkv);
    cudaGetSymbolAddress((void**)&qkv,      g_qkv);
    cudaGetSymbolAddress((void**)&ctxh,     g_ctxh);
    cudaGetSymbolAddress((void**)&attnproj, g_attnproj);
    cudaGetSymbolAddress((void**)&y,        g_y);
    cudaGetSymbolAddress((void**)&yh,       g_yh);
    cudaGetSymbolAddress((void**)&ffhh,     g_ffhh);
    cudaGetSymbolAddress((void**)&ffo,      g_ffo);

    const int gemm_smem = 8 * 1536 * sizeof(unsigned);             // 49152
    const int attn_smem = (2 * 64 * 68 + 8 * 16 * 68 + 64) * sizeof(float); // 69888
    cudaFuncSetAttribute(gemm_h<false, true, false>, cudaFuncAttributeMaxDynamicSharedMemorySize, gemm_smem);
    cudaFuncSetAttribute(gemm_h<true, false, true>,  cudaFuncAttributeMaxDynamicSharedMemorySize, gemm_smem);
    cudaFuncSetAttribute(attn_tc, cudaFuncAttributeMaxDynamicSharedMemorySize, attn_smem);

    // 1) packing: x->half, biases, weights transposed to [n][k] half
    pack_xh<<<TOK * M_DIM / 1024, 256>>>(x);
    pack_bias<<<(QKV_N + 255) / 256, 256>>>(bq, bk, bv);
    {
        dim3 blk(32, 8);
        pack_qkvT<<<dim3(32, 96), blk>>>(Wq, Wk, Wv);
        packT<<<dim3(32, 32), blk>>>(Wo, Woh, M_DIM, M_DIM);
        packT<<<dim3(32, 64), blk>>>(W1, W1h, M_DIM, FFN_H);
        packT<<<dim3(64, 32), blk>>>(W2, W2h, FFN_H, M_DIM);
    }

    // 2) fused QKV projection (half in, float out)
    gemm_h<false, true, false><<<dim3(QKV_N / 128, TOK / 128), 256, gemm_smem>>>(
        xh, Wqkvh, bqkv, qkv, nullptr, TOK, QKV_N, M_DIM);

    // 3) attention (float qkv in, half ctx out)
    attn_tc<<<dim3(S_DIM / 128, B_DIM * NHEAD), 256, attn_smem>>>(qkv, amask, ctxh);

    // 4) output projection
    gemm_h<false, true, false><<<dim3(M_DIM / 128, TOK / 128), 256, gemm_smem>>>(
        ctxh, Woh, bo, attnproj, nullptr, TOK, M_DIM, M_DIM);

    // 5) y = LN(attnproj + x)  (float + half outputs)
    ln_kernel<true><<<TOK, 256>>>(attnproj, x, g1, b1, y, yh);

    // 6) ffh = relu(y @ W1 + bias1)  (half only)
    gemm_h<true, false, true><<<dim3(FFN_H / 128, TOK / 128), 256, gemm_smem>>>(
        yh, W1h, bias1, nullptr, ffhh, TOK, FFN_H, M_DIM);

    // 7) ffo = ffh @ W2 + bias2
    gemm_h<false, true, false><<<dim3(M_DIM / 128, TOK / 128), 256, gemm_smem>>>(
        ffhh, W2h, bias2, ffo, nullptr, TOK, M_DIM, FFN_H);

    // 8) out = LN(y + ffo)
    ln_kernel<false><<<TOK, 256>>>(ffo, y, g2, b2, out, nullptr);
}

// round 12
// speedup vs baseline: 2.2054x; 1.3778x over previous
#include <cuda_runtime.h>
#include <cuda_fp16.h>
#include <stdint.h>
#include <math.h>

#define B_DIM 2
#define S_DIM 2048
#define M_DIM 1024
#define NHEAD 16
#define HDIM 64
#define FFN_H 2048
#define TOK (B_DIM * S_DIM)          // 4096
#define QKV_N (3 * M_DIM)            // 3072
#define NEGV -1e9f

// ------------------------- scratch (static device) -------------------------
__device__ __half g_xh[TOK * M_DIM];           // x in half
__device__ __half g_Wqkvh[QKV_N * M_DIM];      // [n][k] half (transposed)
__device__ __half g_Woh[M_DIM * M_DIM];        // [n][k]
__device__ __half g_W1h[FFN_H * M_DIM];        // [n][k]
__device__ __half g_W2h[M_DIM * FFN_H];        // [n][k]
__device__ float  g_bqkv[QKV_N];
__device__ __half g_qkvh[TOK * QKV_N];         // q|k|v half
__device__ __half g_vTh[B_DIM * M_DIM * S_DIM]; // V transposed [b*1024+h*64+d][s]
__device__ __half g_ctxh[TOK * M_DIM];         // attention out, half
__device__ float  g_attnproj[TOK * M_DIM];
__device__ float  g_y[TOK * M_DIM];
__device__ __half g_yh[TOK * M_DIM];
__device__ __half g_ffhh[TOK * FFN_H];
__device__ float  g_ffo[TOK * M_DIM];

// ------------------------- helpers ------------------------------------
__device__ __forceinline__ void mma16(float* c, const unsigned* a, const unsigned* b) {
    asm volatile(
        "mma.sync.aligned.m16n8k16.row.col.f32.f16.f16.f32 "
        "{%0,%1,%2,%3},{%4,%5,%6,%7},{%8,%9},{%0,%1,%2,%3};"
        : "+f"(c[0]), "+f"(c[1]), "+f"(c[2]), "+f"(c[3])
        : "r"(a[0]), "r"(a[1]), "r"(a[2]), "r"(a[3]), "r"(b[0]), "r"(b[1]));
}
__device__ __forceinline__ void cp16(uint32_t dst, const void* src) {
    asm volatile("cp.async.cg.shared.global [%0], [%1], 16;\n" :: "r"(dst), "l"(src));
}
#define CP_COMMIT() asm volatile("cp.async.commit_group;\n" ::: "memory")
#define CP_WAIT(n)  asm volatile("cp.async.wait_group %0;\n" :: "n"(n) : "memory")
__device__ __forceinline__ unsigned h2u(__half2 h) { return *(unsigned*)&h; }

// ------------------------- pack kernels -------------------------------------
__global__ void pack_xh(const float* __restrict__ x) {
    int i = (blockIdx.x * blockDim.x + threadIdx.x) * 4;
    float4 v = *(const float4*)&x[i];
    __half2* d = (__half2*)&g_xh[i];
    d[0] = __floats2half2_rn(v.x, v.y);
    d[1] = __floats2half2_rn(v.z, v.w);
}
__global__ void pack_bias(const float* __restrict__ bq, const float* __restrict__ bk,
                          const float* __restrict__ bv) {
    int idx = blockIdx.x * blockDim.x + threadIdx.x;
    if (idx < QKV_N) {
        int which = idx / M_DIM, hd = idx % M_DIM;
        const float* bb = (which == 0) ? bq : (which == 1) ? bk : bv;
        g_bqkv[idx] = bb[hd];
    }
}
__global__ void pack_qkvT(const float* __restrict__ Wq, const float* __restrict__ Wk,
                          const float* __restrict__ Wv) {
    __shared__ float t[32][33];
    const int k0 = blockIdx.x * 32, n0 = blockIdx.y * 32;
    const int which = n0 >> 10, hd0 = n0 & 1023, h = hd0 >> 6, d0 = hd0 & 63;
    const float* W = (which == 0) ? Wq : (which == 1) ? Wk : Wv;
    const int tx = threadIdx.x, ty = threadIdx.y;
#pragma unroll
    for (int yy = ty; yy < 32; yy += 8)
        t[yy][tx] = W[((size_t)(h << 10) + k0 + yy) * 64 + d0 + tx];
    __syncthreads();
#pragma unroll
    for (int yy = ty; yy < 32; yy += 8)
        g_Wqkvh[(size_t)(n0 + yy) * M_DIM + k0 + tx] = __float2half_rn(t[tx][yy]);
}
__global__ void packT(const float* __restrict__ src, __half* __restrict__ dst,
                      int K, int N) {
    __shared__ float t[32][33];
    const int k0 = blockIdx.x * 32, n0 = blockIdx.y * 32;
    const int tx = threadIdx.x, ty = threadIdx.y;
#pragma unroll
    for (int yy = ty; yy < 32; yy += 8)
        t[yy][tx] = src[(size_t)(k0 + yy) * N + n0 + tx];
    __syncthreads();
#pragma unroll
    for (int yy = ty; yy < 32; yy += 8)
        dst[(size_t)(n0 + yy) * K + k0 + tx] = __float2half_rn(t[tx][yy]);
}

// ------------------------- fp16 tensor-core GEMM (cp.async 4-stage) --------
// C = A[M,K] @ Bt[N,K]^T + bias, fp32 accum. Optional ReLU.
// WF: write float C. WH: write half C. VT: additionally scatter V block
// (cols >= 2048) transposed into vT[b*1024+hd][s] (QKV gemm only).
template <bool RELU, bool WF, bool WH, bool VT>
__global__ __launch_bounds__(256, 2)
void gemm_h(const __half* __restrict__ A, const __half* __restrict__ Bt,
            const float* __restrict__ bias, float* __restrict__ Cf,
            __half* __restrict__ Ch, __half* __restrict__ vT,
            int M, int N, int K) {
    extern __shared__ unsigned smw[];
    unsigned* As = smw;                 // 4 * 1536
    unsigned* Bs = smw + 4 * 1536;      // 4 * 1536

    const int tid = threadIdx.x, lane = tid & 31, w = tid >> 5;
    const int wm = w >> 2, wn = w & 3;
    const int g = lane >> 2, tg = lane & 3;
    const int row0 = blockIdx.y * 128, col0 = blockIdx.x * 128;

    const int r = tid >> 1, sel = tid & 1;
    const __half* Agp = A + (size_t)(row0 + r) * K + sel * 8;
    const __half* Bgp = Bt + (size_t)(col0 + r) * K + sel * 8;

    uint32_t smA = (uint32_t)__cvta_generic_to_shared(As);
    uint32_t smB = (uint32_t)__cvta_generic_to_shared(Bs);
    const uint32_t dA = smA + (r * 12 + sel * 4) * 4;
    const uint32_t dB = smB + (r * 12 + sel * 4) * 4;

    float acc[4][4][4];
#pragma unroll
    for (int i = 0; i < 4; i++)
#pragma unroll
        for (int j = 0; j < 4; j++)
#pragma unroll
            for (int q = 0; q < 4; q++) acc[i][j][q] = 0.f;

    const int T = K >> 4;

    auto issue = [&](int s, int k0) {
        cp16(dA + s * 6144, Agp + k0);
        cp16(dB + s * 6144, Bgp + k0);
        CP_COMMIT();
    };

    issue(0, 0);
    issue(1, 16);
    issue(2, 32);

    for (int t = 0; t < T; t++) {
        CP_WAIT(2);
        __syncthreads();

        const int cur = t & 3;
        const unsigned* as = As + cur * 1536;
        const unsigned* bs = Bs + cur * 1536;

        unsigned af[4][4];
#pragma unroll
        for (int mi = 0; mi < 4; mi++) {
            const unsigned* ap = as + (wm * 64 + mi * 16) * 12;
            af[mi][0] = ap[g * 12 + tg];
            af[mi][1] = ap[(g + 8) * 12 + tg];
            af[mi][2] = ap[g * 12 + tg + 4];
            af[mi][3] = ap[(g + 8) * 12 + tg + 4];
        }
#pragma unroll
        for (int ni = 0; ni < 4; ni++) {
            const unsigned* bw = bs + (wn * 32 + ni * 8 + g) * 12;
            unsigned bf[2];
            bf[0] = bw[tg];
            bf[1] = bw[tg + 4];
#pragma unroll
            for (int mi = 0; mi < 4; mi++) mma16(acc[mi][ni], af[mi], bf);
        }

        if (t + 3 < T) issue((t + 3) & 3, (t + 3) * 16);
        else           CP_COMMIT();
    }

    // epilogue
#pragma unroll
    for (int mi = 0; mi < 4; mi++) {
        const int rr = row0 + wm * 64 + mi * 16 + g;
#pragma unroll
        for (int ni = 0; ni < 4; ni++) {
            const int c = col0 + wn * 32 + ni * 8 + 2 * tg;
            const float b0 = bias[c], b1 = bias[c + 1];
            float v0 = acc[mi][ni][0] + b0, v1 = acc[mi][ni][1] + b1;
            float v2 = acc[mi][ni][2] + b0, v3 = acc[mi][ni][3] + b1;
            if (RELU) {
                v0 = fmaxf(v0, 0.f); v1 = fmaxf(v1, 0.f);
                v2 = fmaxf(v2, 0.f); v3 = fmaxf(v3, 0.f);
            }
            if (WF) {
                *(float2*)&Cf[(size_t)rr * N + c] = make_float2(v0, v1);
                *(float2*)&Cf[(size_t)(rr + 8) * N + c] = make_float2(v2, v3);
            }
            if (WH) {
                *(__half2*)&Ch[(size_t)rr * N + c] = __floats2half2_rn(v0, v1);
                *(__half2*)&Ch[(size_t)(rr + 8) * N + c] = __floats2half2_rn(v2, v3);
            }
            if (VT) {
                if (c >= 2 * M_DIM) {
                    const int bb = rr >> 11, ss = rr & 2047;
                    const int hd = c - 2 * M_DIM;
                    __half* p0 = vT + (size_t)(bb * M_DIM + hd) * S_DIM + ss;
                    p0[0] = __float2half_rn(v0);
                    p0[8] = __float2half_rn(v2);
                    p0[S_DIM]     = __float2half_rn(v1);
                    p0[S_DIM + 8] = __float2half_rn(v3);
                }
            }
        }
    }
}

// ------------------------- fp16 flash attention ----------------------------
// grid (S/128, B*H), 256 thr = 8 warps; warp = 16 queries; key tile 64.
// K tile: [64 keys][64 dims] half, rows stride 36 words. V^T tile:
// [64 dims][64 keys] half from g_vTh, same stride. 3-stage cp.async.
// P fragments built directly from S output registers (no smem round-trip).
__global__ __launch_bounds__(256, 2)
void attn_h(const __half* __restrict__ qkvh, const __half* __restrict__ vTh,
            const int* __restrict__ mask, __half* __restrict__ ctx) {
    extern __shared__ unsigned smu[];
    float* Msf = (float*)(smu + 3 * 4608);      // [3][64]

    const int tid = threadIdx.x, lane = tid & 31, w = tid >> 5;
    const int g = lane >> 2, tg = lane & 3;
    const int bh = blockIdx.y, b = bh >> 4, h = bh & 15;
    const int qw = blockIdx.x * 128 + w * 16;

    uint32_t smb = (uint32_t)__cvta_generic_to_shared(smu);

    // Q fragments (half2 words), pre-scaled by 0.125
    unsigned qf[4][4];
    {
        const __half2 sc = __float2half2_rn(0.125f);
        const __half* qb = qkvh + (size_t)(b * S_DIM + qw + g) * QKV_N + h * HDIM;
        const __half* qb8 = qb + (size_t)8 * QKV_N;
#pragma unroll
        for (int fk = 0; fk < 4; fk++) {
            qf[fk][0] = h2u(__hmul2(*(const __half2*)&qb [fk * 16 + 2 * tg], sc));
            qf[fk][1] = h2u(__hmul2(*(const __half2*)&qb8[fk * 16 + 2 * tg], sc));
            qf[fk][2] = h2u(__hmul2(*(const __half2*)&qb [fk * 16 + 8 + 2 * tg], sc));
            qf[fk][3] = h2u(__hmul2(*(const __half2*)&qb8[fk * 16 + 8 + 2 * tg], sc));
        }
    }

    float of[8][4];
#pragma unroll
    for (int i = 0; i < 8; i++) { of[i][0] = of[i][1] = of[i][2] = of[i][3] = 0.f; }
    float m0 = -INFINITY, m1 = -INFINITY, l0 = 0.f, l1 = 0.f;

    const int key = tid >> 2, c0 = tid & 3;
    auto issue = [&](int s, int kt) {
        const __half* srcK = qkvh + (size_t)(b * S_DIM + kt + key) * QKV_N + M_DIM + h * HDIM;
        const __half* srcV = vTh + (size_t)(b * M_DIM + h * HDIM + key) * S_DIM + kt;
        const uint32_t dK = smb + (s * 4608 + key * 36) * 4;
        const uint32_t dV = dK + 2304 * 4;
#pragma unroll
        for (int i = 0; i < 2; i++) {
            const int c = c0 + i * 4;
            cp16(dK + c * 16, srcK + c * 8);
            cp16(dV + c * 16, srcV + c * 8);
        }
        CP_COMMIT();
        if (tid < 64) Msf[s * 64 + tid] = mask[b * S_DIM + kt + tid] ? 0.f : NEGV;
    };

    const int T = S_DIM / 64;
    issue(0, 0);
    issue(1, 64);

    for (int t = 0; t < T; t++) {
        CP_WAIT(1);
        __syncthreads();

        const int cur = t % 3;
        const unsigned* Kw = smu + cur * 4608;
        const unsigned* Vw = Kw + 2304;
        const float* Ms = Msf + cur * 64;

        // S = Q * K^T  (16 x 64 per warp), fp16 mma
        float s[8][4];
#pragma unroll
        for (int fn = 0; fn < 8; fn++) { s[fn][0] = s[fn][1] = s[fn][2] = s[fn][3] = 0.f; }
#pragma unroll
        for (int fk = 0; fk < 4; fk++) {
#pragma unroll
            for (int fn = 0; fn < 8; fn++) {
                const unsigned* kw = Kw + (fn * 8 + g) * 36 + fk * 8;
                unsigned bf[2];
                bf[0] = kw[tg];
                bf[1] = kw[tg + 4];
                mma16(s[fn], qf[fk], bf);
            }
        }

        // mask + online softmax (rows g, g+8)
        float mx0 = -INFINITY, mx1 = -INFINITY;
#pragma unroll
        for (int fn = 0; fn < 8; fn++) {
            const float mk0 = Ms[fn * 8 + 2 * tg], mk1 = Ms[fn * 8 + 2 * tg + 1];
            s[fn][0] += mk0; s[fn][1] += mk1;
            s[fn][2] += mk0; s[fn][3] += mk1;
            mx0 = fmaxf(mx0, fmaxf(s[fn][0], s[fn][1]));
            mx1 = fmaxf(mx1, fmaxf(s[fn][2], s[fn][3]));
        }
        mx0 = fmaxf(mx0, __shfl_xor_sync(0xffffffffu, mx0, 1));
        mx0 = fmaxf(mx0, __shfl_xor_sync(0xffffffffu, mx0, 2));
        mx1 = fmaxf(mx1, __shfl_xor_sync(0xffffffffu, mx1, 1));
        mx1 = fmaxf(mx1, __shfl_xor_sync(0xffffffffu, mx1, 2));
        const float nm0 = fmaxf(m0, mx0), nm1 = fmaxf(m1, mx1);
        const float a0 = __expf(m0 - nm0), a1 = __expf(m1 - nm1);
        m0 = nm0; m1 = nm1;
        l0 *= a0; l1 *= a1;
#pragma unroll
        for (int fn = 0; fn < 8; fn++) {
            of[fn][0] *= a0; of[fn][1] *= a0;
            of[fn][2] *= a1; of[fn][3] *= a1;
            s[fn][0] = __expf(s[fn][0] - m0);
            s[fn][1] = __expf(s[fn][1] - m0);
            s[fn][2] = __expf(s[fn][2] - m1);
            s[fn][3] = __expf(s[fn][3] - m1);
            l0 += s[fn][0] + s[fn][1];
            l1 += s[fn][2] + s[fn][3];
        }

        // P fragments directly from registers (C layout == A layout pairing)
        unsigned pf[4][4];
#pragma unroll
        for (int j = 0; j < 4; j++) {
            pf[j][0] = h2u(__floats2half2_rn(s[2 * j][0],     s[2 * j][1]));
            pf[j][1] = h2u(__floats2half2_rn(s[2 * j][2],     s[2 * j][3]));
            pf[j][2] = h2u(__floats2half2_rn(s[2 * j + 1][0], s[2 * j + 1][1]));
            pf[j][3] = h2u(__floats2half2_rn(s[2 * j + 1][2], s[2 * j + 1][3]));
        }

        // O += P * V  (V^T words from smem)
#pragma unroll
        for (int j = 0; j < 4; j++) {
#pragma unroll
            for (int fn = 0; fn < 8; fn++) {
                const unsigned* vw = Vw + (fn * 8 + g) * 36 + j * 8;
                unsigned bf[2];
                bf[0] = vw[tg];
                bf[1] = vw[tg + 4];
                mma16(of[fn], pf[j], bf);
            }
        }

        if (t + 2 < T) issue((t + 2) % 3, (t + 2) * 64);
        else           CP_COMMIT();
    }

    l0 += __shfl_xor_sync(0xffffffffu, l0, 1);
    l0 += __shfl_xor_sync(0xffffffffu, l0, 2);
    l1 += __shfl_xor_sync(0xffffffffu, l1, 1);
    l1 += __shfl_xor_sync(0xffffffffu, l1, 2);

    const float i0 = 1.f / fmaxf(l0, 1e-30f), i1 = 1.f / fmaxf(l1, 1e-30f);
    __half* cb = ctx + (size_t)(b * S_DIM + qw) * M_DIM + h * HDIM;
#pragma unroll
    for (int fn = 0; fn < 8; fn++) {
        *(__half2*)&cb[(size_t)g * M_DIM + fn * 8 + 2 * tg] =
            __floats2half2_rn(of[fn][0] * i0, of[fn][1] * i0);
        *(__half2*)&cb[(size_t)(g + 8) * M_DIM + fn * 8 + 2 * tg] =
            __floats2half2_rn(of[fn][2] * i1, of[fn][3] * i1);
    }
}

// ------------------------- residual + layernorm ----------------------------
template <bool WH>
__global__ __launch_bounds__(256)
void ln_kernel(const float* __restrict__ A, const float* __restrict__ R,
               const float* __restrict__ g, const float* __restrict__ be,
               float* __restrict__ out, __half* __restrict__ outh) {
    __shared__ float red[8];
    __shared__ float bcast;
    const int row = blockIdx.x;
    const int tid = threadIdx.x;

    float4 a = ((const float4*)(A + (size_t)row * M_DIM))[tid];
    float4 r = ((const float4*)(R + (size_t)row * M_DIM))[tid];
    float v0 = a.x + r.x, v1 = a.y + r.y, v2 = a.z + r.z, v3 = a.w + r.w;

    float s = v0 + v1 + v2 + v3;
#pragma unroll
    for (int off = 16; off; off >>= 1) s += __shfl_xor_sync(0xffffffffu, s, off);
    if ((tid & 31) == 0) red[tid >> 5] = s;
    __syncthreads();
    if (tid == 0) {
        float t = 0.f;
#pragma unroll
        for (int i = 0; i < 8; i++) t += red[i];
        bcast = t * (1.f / M_DIM);
    }
    __syncthreads();
    const float mu = bcast;

    float d0 = v0 - mu, d1 = v1 - mu, d2 = v2 - mu, d3 = v3 - mu;
    float s2 = d0 * d0 + d1 * d1 + d2 * d2 + d3 * d3;
#pragma unroll
    for (int off = 16; off; off >>= 1) s2 += __shfl_xor_sync(0xffffffffu, s2, off);
    __syncthreads();
    if ((tid & 31) == 0) red[tid >> 5] = s2;
    __syncthreads();
    if (tid == 0) {
        float t = 0.f;
#pragma unroll
        for (int i = 0; i < 8; i++) t += red[i];
        bcast = rsqrtf(t * (1.f / M_DIM) + 1e-5f);
    }
    __syncthreads();
    const float rstd = bcast;

    float4 gg = ((const float4*)g)[tid];
    float4 bb = ((const float4*)be)[tid];
    float4 o;
    o.x = d0 * rstd * gg.x + bb.x;
    o.y = d1 * rstd * gg.y + bb.y;
    o.z = d2 * rstd * gg.z + bb.z;
    o.w = d3 * rstd * gg.w + bb.w;
    ((float4*)(out + (size_t)row * M_DIM))[tid] = o;
    if (WH) {
        __half2* hd = (__half2*)&outh[(size_t)row * M_DIM + tid * 4];
        hd[0] = __floats2half2_rn(o.x, o.y);
        hd[1] = __floats2half2_rn(o.z, o.w);
    }
}

// ---------------------------------------------------------------------------
extern "C" void kernel_launch(void* const* d_in, const int* in_sizes, int n_in,
                              void* d_out, int out_size) {
    const float* x     = (const float*)d_in[0];
    const int*   amask = (const int*)  d_in[1];
    const float* Wq    = (const float*)d_in[2];
    const float* bq    = (const float*)d_in[3];
    const float* Wk    = (const float*)d_in[4];
    const float* bk    = (const float*)d_in[5];
    const float* Wv    = (const float*)d_in[6];
    const float* bv    = (const float*)d_in[7];
    const float* Wo    = (const float*)d_in[8];
    const float* bo    = (const float*)d_in[9];
    const float* g1    = (const float*)d_in[10];
    const float* b1    = (const float*)d_in[11];
    const float* W1    = (const float*)d_in[12];
    const float* bias1 = (const float*)d_in[13];
    const float* W2    = (const float*)d_in[14];
    const float* bias2 = (const float*)d_in[15];
    const float* g2    = (const float*)d_in[16];
    const float* b2    = (const float*)d_in[17];
    float* out = (float*)d_out;

    __half *xh, *Wqkvh, *Woh, *W1h, *W2h, *qkvh, *vTh, *ctxh, *yh, *ffhh;
    float *bqkv, *attnproj, *y, *ffo;
    cudaGetSymbolAddress((void**)&xh,       g_xh);
    cudaGetSymbolAddress((void**)&Wqkvh,    g_Wqkvh);
    cudaGetSymbolAddress((void**)&Woh,      g_Woh);
    cudaGetSymbolAddress((void**)&W1h,      g_W1h);
    cudaGetSymbolAddress((void**)&W2h,      g_W2h);
    cudaGetSymbolAddress((void**)&bqkv,     g_bqkv);
    cudaGetSymbolAddress((void**)&qkvh,     g_qkvh);
    cudaGetSymbolAddress((void**)&vTh,      g_vTh);
    cudaGetSymbolAddress((void**)&ctxh,     g_ctxh);
    cudaGetSymbolAddress((void**)&attnproj, g_attnproj);
    cudaGetSymbolAddress((void**)&y,        g_y);
    cudaGetSymbolAddress((void**)&yh,       g_yh);
    cudaGetSymbolAddress((void**)&ffhh,     g_ffhh);
    cudaGetSymbolAddress((void**)&ffo,      g_ffo);

    const int gemm_smem = 8 * 1536 * sizeof(unsigned);             // 49152
    const int attn_smem = 3 * 4608 * 4 + 3 * 64 * 4;               // 56064
    cudaFuncSetAttribute(gemm_h<false, false, true, true>,  cudaFuncAttributeMaxDynamicSharedMemorySize, gemm_smem);
    cudaFuncSetAttribute(gemm_h<false, true, false, false>, cudaFuncAttributeMaxDynamicSharedMemorySize, gemm_smem);
    cudaFuncSetAttribute(gemm_h<true, false, true, false>,  cudaFuncAttributeMaxDynamicSharedMemorySize, gemm_smem);
    cudaFuncSetAttribute(attn_h, cudaFuncAttributeMaxDynamicSharedMemorySize, attn_smem);

    // 1) packing
    pack_xh<<<TOK * M_DIM / 1024, 256>>>(x);
    pack_bias<<<(QKV_N + 255) / 256, 256>>>(bq, bk, bv);
    {
        dim3 blk(32, 8);
        pack_qkvT<<<dim3(32, 96), blk>>>(Wq, Wk, Wv);
        packT<<<dim3(32, 32), blk>>>(Wo, Woh, M_DIM, M_DIM);
        packT<<<dim3(32, 64), blk>>>(W1, W1h, M_DIM, FFN_H);
        packT<<<dim3(64, 32), blk>>>(W2, W2h, FFN_H, M_DIM);
    }

    // 2) fused QKV projection (half out + transposed V scatter)
    gemm_h<false, false, true, true><<<dim3(QKV_N / 128, TOK / 128), 256, gemm_smem>>>(
        xh, Wqkvh, bqkv, nullptr, qkvh, vTh, TOK, QKV_N, M_DIM);

    // 3) attention (all fp16 datapath, fp32 softmax/accum)
    attn_h<<<dim3(S_DIM / 128, B_DIM * NHEAD), 256, attn_smem>>>(qkvh, vTh, amask, ctxh);

    // 4) output projection
    gemm_h<false, true, false, false><<<dim3(M_DIM / 128, TOK / 128), 256, gemm_smem>>>(
        ctxh, Woh, bo, attnproj, nullptr, nullptr, TOK, M_DIM, M_DIM);

    // 5) y = LN(attnproj + x)
    ln_kernel<true><<<TOK, 256>>>(attnproj, x, g1, b1, y, yh);

    // 6) ffh = relu(y @ W1 + bias1)
    gemm_h<true, false, true, false><<<dim3(FFN_H / 128, TOK / 128), 256, gemm_smem>>>(
        yh, W1h, bias1, nullptr, ffhh, nullptr, TOK, FFN_H, M_DIM);

    // 7) ffo = ffh @ W2 + bias2
    gemm_h<false, true, false, false><<<dim3(M_DIM / 128, TOK / 128), 256, gemm_smem>>>(
        ffhh, W2h, bias2, ffo, nullptr, nullptr, TOK, M_DIM, FFN_H);

    // 8) out = LN(y + ffo)
    ln_kernel<false><<<TOK, 256>>>(ffo, y, g2, b2, out, nullptr);
}